// round 7
// baseline (speedup 1.0000x reference)
#include <cuda_runtime.h>
#include <cstdint>

// Problem constants (fixed by setup_inputs)
#define N_NODES 8192
#define IN_DIM  256
#define OUT_DIM 64
#define SLOPE   0.2f

// Scratch (allocation-free rule: __device__ globals)
__device__ float g_proj[N_NODES * OUT_DIM];   // 2 MB
__device__ float g_si[N_NODES];
__device__ float g_sj[N_NODES];

// ---------------------------------------------------------------------------
// Kernel 1: proj = X[8192,256] @ W[256,64] + fused s_i/s_j epilogue.
// BM=32 (grid=256 -> ~2 blocks/SM for cross-block latency hiding),
// 256 threads, each thread owns 1 row x 8 cols. Double-buffered smem.
// ---------------------------------------------------------------------------
#define GM_BM 32
#define GM_BK 32
#define AS_LD 33   // 32 + 1 pad

__global__ __launch_bounds__(256) void gemm_proj_kernel(
    const float* __restrict__ X, const float* __restrict__ W,
    const float* __restrict__ a)
{
    __shared__ float As[2][GM_BK * AS_LD];   // [k][m]
    __shared__ float Bs[2][GM_BK][OUT_DIM];  // [k][n]
    __shared__ float a_s[2 * OUT_DIM];

    const int tid = threadIdx.x;
    const int block_row = blockIdx.x * GM_BM;
    const int row = tid >> 3;        // 0..31
    const int cg  = tid & 7;         // col group, cols cg*8 .. +7

    if (tid < 128) a_s[tid] = a[tid];

    // cooperative load indices
    const int a_r  = tid >> 3;            // 0..31  (256 float4 for A)
    const int a_c4 = tid & 7;
    const int b_r0 = tid >> 4;            // 0..15  (512 float4 for B)
    const int b_c4 = tid & 15;
    const int b_r1 = (tid + 256) >> 4;    // 16..31

    float4 rA, rB0, rB1;

    auto load_tiles = [&](int k0) {
        rA  = *(const float4*)(X + (size_t)(block_row + a_r) * IN_DIM + k0 + a_c4 * 4);
        rB0 = *(const float4*)(W + (size_t)(k0 + b_r0) * OUT_DIM + b_c4 * 4);
        rB1 = *(const float4*)(W + (size_t)(k0 + b_r1) * OUT_DIM + b_c4 * 4);
    };
    auto store_tiles = [&](int buf) {
        As[buf][(a_c4 * 4 + 0) * AS_LD + a_r] = rA.x;
        As[buf][(a_c4 * 4 + 1) * AS_LD + a_r] = rA.y;
        As[buf][(a_c4 * 4 + 2) * AS_LD + a_r] = rA.z;
        As[buf][(a_c4 * 4 + 3) * AS_LD + a_r] = rA.w;
        *(float4*)&Bs[buf][b_r0][b_c4 * 4] = rB0;
        *(float4*)&Bs[buf][b_r1][b_c4 * 4] = rB1;
    };

    float acc[8];
    #pragma unroll
    for (int j = 0; j < 8; j++) acc[j] = 0.0f;

    load_tiles(0);
    store_tiles(0);
    __syncthreads();

    const int NT = IN_DIM / GM_BK;   // 8 k-tiles
    for (int t = 0; t < NT; t++) {
        int buf = t & 1;
        if (t + 1 < NT) load_tiles((t + 1) * GM_BK);

        #pragma unroll
        for (int k = 0; k < GM_BK; k++) {
            float av = As[buf][k * AS_LD + row];
            float4 b0 = *(const float4*)&Bs[buf][k][cg * 8];
            float4 b1 = *(const float4*)&Bs[buf][k][cg * 8 + 4];
            acc[0] = fmaf(av, b0.x, acc[0]);
            acc[1] = fmaf(av, b0.y, acc[1]);
            acc[2] = fmaf(av, b0.z, acc[2]);
            acc[3] = fmaf(av, b0.w, acc[3]);
            acc[4] = fmaf(av, b1.x, acc[4]);
            acc[5] = fmaf(av, b1.y, acc[5]);
            acc[6] = fmaf(av, b1.z, acc[6]);
            acc[7] = fmaf(av, b1.w, acc[7]);
        }
        if (t + 1 < NT) store_tiles(buf ^ 1);
        __syncthreads();
    }

    // store proj
    int grow = block_row + row;
    *(float4*)(g_proj + (size_t)grow * OUT_DIM + cg * 8)     =
        make_float4(acc[0], acc[1], acc[2], acc[3]);
    *(float4*)(g_proj + (size_t)grow * OUT_DIM + cg * 8 + 4) =
        make_float4(acc[4], acc[5], acc[6], acc[7]);

    // fused s epilogue: q = acc . a over this thread's 8 cols, reduce across
    // the 8 col-group threads of the same row (lanes (row&3)*8 + cg).
    float q0 = 0.0f, q1 = 0.0f;
    #pragma unroll
    for (int j = 0; j < 8; j++) {
        q0 = fmaf(acc[j], a_s[cg * 8 + j], q0);
        q1 = fmaf(acc[j], a_s[64 + cg * 8 + j], q1);
    }
    #pragma unroll
    for (int o = 4; o > 0; o >>= 1) {
        q0 += __shfl_down_sync(0xffffffffu, q0, o, 8);
        q1 += __shfl_down_sync(0xffffffffu, q1, o, 8);
    }
    if (cg == 0) { g_si[grow] = q0; g_sj[grow] = q1; }
}

// ---------------------------------------------------------------------------
// Kernel 2: per-row sparse softmax-attention (R3 shape, improved).
// One 256-thread block per row, ~6 resident blocks/SM: each block's gather
// hides under other blocks' DRAM scans. Adjacency read with __ldcs
// (evict-first) so proj/s_j stay L2-resident for the gather.
// Single-pass per-warp ballot compaction into 8 segments of <=128 (warp w
// covers nodes [w*1024,(w+1)*1024); expected 10.2 edges, cap 128 ~ 36 sigma).
// ---------------------------------------------------------------------------
#define SEG 128

__device__ __forceinline__ float leaky(float x) {
    return x > 0.0f ? x : SLOPE * x;
}

__device__ __forceinline__ float block_reduce(float v, float* s8, bool do_max)
{
    int lane = threadIdx.x & 31;
    int warp = threadIdx.x >> 5;
    #pragma unroll
    for (int o = 16; o > 0; o >>= 1) {
        float t = __shfl_xor_sync(0xffffffffu, v, o);
        v = do_max ? fmaxf(v, t) : (v + t);
    }
    __syncthreads();
    if (lane == 0) s8[warp] = v;
    __syncthreads();
    if (threadIdx.x == 0) {
        float r = s8[0];
        #pragma unroll
        for (int w = 1; w < 8; w++)
            r = do_max ? fmaxf(r, s8[w]) : (r + s8[w]);
        s8[0] = r;
    }
    __syncthreads();
    return s8[0];
}

__global__ __launch_bounds__(256) void attn_kernel(
    const unsigned* __restrict__ adj, float* __restrict__ out)
{
    __shared__ unsigned short s_id[8 * SEG];   // 2 KB
    __shared__ float s_w[8 * SEG];             // 4 KB
    __shared__ float s_acc[4 * OUT_DIM];       // 1 KB
    __shared__ float s_red[8];
    __shared__ int   s_wc[8];

    const int row  = blockIdx.x;
    const int tid  = threadIdx.x;
    const int lane = tid & 31;
    const int warp = tid >> 5;

    const uint4* arow4 = (const uint4*)(adj + (size_t)row * N_NODES); // 2048 uint4

    // ---- single-pass scan + per-warp ballot compaction ----
    {
        uint4 v[8];
        #pragma unroll
        for (int i = 0; i < 8; i++)
            v[i] = __ldcs(arow4 + warp * 256 + i * 32 + lane);   // evict-first

        int wcnt = 0;
        const unsigned lt = (1u << lane) - 1u;
        #pragma unroll
        for (int i = 0; i < 8; i++) {
            unsigned vals[4] = {v[i].x, v[i].y, v[i].z, v[i].w};
            #pragma unroll
            for (int c = 0; c < 4; c++) {
                unsigned m = __ballot_sync(0xffffffffu, vals[c] != 0u);
                if (m & (1u << lane)) {
                    int pos = wcnt + __popc(m & lt);
                    if (pos < SEG)
                        s_id[warp * SEG + pos] =
                            (unsigned short)(warp * 1024 + i * 128 + 4 * lane + c);
                }
                wcnt += __popc(m);
            }
        }
        if (lane == 0) s_wc[warp] = wcnt;
    }
    __syncthreads();

    int cnt = 0;
    bool overflow = false;
    #pragma unroll
    for (int w = 0; w < 8; w++) {
        int c = s_wc[w];
        cnt += c;
        overflow |= (c > SEG);
    }

    const float si_r = g_si[row];
    const int   g    = tid >> 6;      // group 0..3
    const int   d    = tid & 63;      // output dim

    if (cnt > 0 && !overflow) {
        // ---------------- fast path ----------------
        // e + local max: 4 passes, each covering 2 segments with all 256 thr
        float lm = -INFINITY;
        #pragma unroll
        for (int sp = 0; sp < 4; sp++) {
            int seg = sp * 2 + (tid >> 7);
            int k   = tid & 127;
            if (k < s_wc[seg]) {
                float e = leaky(si_r + g_sj[s_id[seg * SEG + k]]);
                s_w[seg * SEG + k] = e;
                lm = fmaxf(lm, e);
            }
        }
        float m = block_reduce(lm, s_red, true);

        float ls = 0.0f;
        #pragma unroll
        for (int sp = 0; sp < 4; sp++) {
            int seg = sp * 2 + (tid >> 7);
            int k   = tid & 127;
            if (k < s_wc[seg]) {
                float w = __expf(s_w[seg * SEG + k] - m);
                s_w[seg * SEG + k] = w;
                ls += w;
            }
        }
        float denom = block_reduce(ls, s_red, false);

        float acc = 0.0f;
        #pragma unroll
        for (int seg = 0; seg < 8; seg++) {
            int cs = s_wc[seg];
            #pragma unroll 4
            for (int k = g; k < cs; k += 4)
                acc += s_w[seg * SEG + k]
                     * g_proj[(size_t)s_id[seg * SEG + k] * OUT_DIM + d];
        }
        s_acc[g * OUT_DIM + d] = acc;
        __syncthreads();
        if (g == 0) {
            float tot = s_acc[0 * OUT_DIM + d] + s_acc[1 * OUT_DIM + d]
                      + s_acc[2 * OUT_DIM + d] + s_acc[3 * OUT_DIM + d];
            out[(size_t)row * OUT_DIM + d] = tot / denom;
        }
        return;
    }

    if (cnt == 0) {
        // softmax over all-NEG_BIG row is uniform: out = mean(proj)
        float acc = 0.0f;
        for (int j = g; j < N_NODES; j += 4)
            acc += g_proj[(size_t)j * OUT_DIM + d];
        s_acc[g * OUT_DIM + d] = acc;
        __syncthreads();
        if (g == 0) {
            float tot = s_acc[0 * OUT_DIM + d] + s_acc[1 * OUT_DIM + d]
                      + s_acc[2 * OUT_DIM + d] + s_acc[3 * OUT_DIM + d];
            out[(size_t)row * OUT_DIM + d] = tot * (1.0f / (float)N_NODES);
        }
        return;
    }

    // ---- overflow fallback (segment > 128, ~never): direct rescan ----
    const unsigned* arow = adj + (size_t)row * N_NODES;
    float lm = -INFINITY;
    for (int j = tid; j < N_NODES; j += 256)
        if (arow[j]) lm = fmaxf(lm, leaky(si_r + g_sj[j]));
    float m = block_reduce(lm, s_red, true);

    float ls = 0.0f;
    for (int j = tid; j < N_NODES; j += 256)
        if (arow[j]) ls += __expf(leaky(si_r + g_sj[j]) - m);
    float denom = block_reduce(ls, s_red, false);

    float acc = 0.0f;
    for (int j = g; j < N_NODES; j += 4)
        if (arow[j]) {
            float w = __expf(leaky(si_r + g_sj[j]) - m);
            acc += w * g_proj[(size_t)j * OUT_DIM + d];
        }
    s_acc[g * OUT_DIM + d] = acc;
    __syncthreads();
    if (g == 0) {
        float tot = s_acc[0 * OUT_DIM + d] + s_acc[1 * OUT_DIM + d]
                  + s_acc[2 * OUT_DIM + d] + s_acc[3 * OUT_DIM + d];
        out[(size_t)row * OUT_DIM + d] = tot / denom;
    }
}

// ---------------------------------------------------------------------------
// Launch
// ---------------------------------------------------------------------------
extern "C" void kernel_launch(void* const* d_in, const int* in_sizes, int n_in,
                              void* d_out, int out_size)
{
    const float*    X   = (const float*)d_in[0];
    const unsigned* adj = (const unsigned*)d_in[1];   // bool widened to 32-bit
    const float*    W   = (const float*)d_in[2];
    const float*    a   = (const float*)d_in[3];
    float*          out = (float*)d_out;

    gemm_proj_kernel<<<N_NODES / GM_BM, 256>>>(X, W, a);
    attn_kernel<<<N_NODES, 256>>>(adj, out);
}

// round 8
// speedup vs baseline: 1.7113x; 1.7113x over previous
#include <cuda_runtime.h>
#include <cstdint>

// Problem constants (fixed by setup_inputs)
#define N_NODES 8192
#define IN_DIM  256
#define OUT_DIM 64
#define SLOPE   0.2f

// Scratch (allocation-free rule: __device__ globals)
__device__ float g_proj[N_NODES * OUT_DIM];   // 2 MB
__device__ float g_si[N_NODES];
__device__ float g_sj[N_NODES];

// ---------------------------------------------------------------------------
// Kernel 1: proj = X[8192,256] @ W[256,64] + fused s_i/s_j epilogue.
// BM=32 (grid=256 -> all SMs busy), 128 threads, 4x4 microtile per thread
// (8 smem floats per 16 FMAs), double-buffered smem + register prefetch.
// ---------------------------------------------------------------------------
#define GM_BM 32
#define GM_BK 32
#define AS_LD 36   // 32 + 4 pad

__global__ __launch_bounds__(128) void gemm_proj_kernel(
    const float* __restrict__ X, const float* __restrict__ W,
    const float* __restrict__ a)
{
    __shared__ float As[2][GM_BK * AS_LD];   // [k][m], padded
    __shared__ float Bs[2][GM_BK][OUT_DIM];  // [k][n]
    __shared__ float a_s[2 * OUT_DIM];

    const int tid = threadIdx.x;
    const int block_row = blockIdx.x * GM_BM;
    const int trow = tid >> 4;   // 0..7  -> rows trow*4 .. +3
    const int tcol = tid & 15;   // 0..15 -> cols tcol*4 .. +3

    a_s[tid] = a[tid];           // 128 threads load all 128 a values

    // cooperative load indices
    // A tile: 32 rows x 32 k = 256 float4 -> 2 per thread
    const int a_r0 = tid >> 3;             // 0..15
    const int a_c0 = tid & 7;
    const int a_r1 = (tid + 128) >> 3;     // 16..31
    // B tile: 32 k x 64 n = 512 float4 -> 4 per thread
    const int b_c4 = tid & 15;
    const int b_r0 = tid >> 4;             // 0..7
    const int b_r1 = (tid + 128) >> 4;     // 8..15
    const int b_r2 = (tid + 256) >> 4;     // 16..23
    const int b_r3 = (tid + 384) >> 4;     // 24..31

    float4 rA0, rA1, rB0, rB1, rB2, rB3;

    auto load_tiles = [&](int k0) {
        rA0 = *(const float4*)(X + (size_t)(block_row + a_r0) * IN_DIM + k0 + a_c0 * 4);
        rA1 = *(const float4*)(X + (size_t)(block_row + a_r1) * IN_DIM + k0 + a_c0 * 4);
        rB0 = *(const float4*)(W + (size_t)(k0 + b_r0) * OUT_DIM + b_c4 * 4);
        rB1 = *(const float4*)(W + (size_t)(k0 + b_r1) * OUT_DIM + b_c4 * 4);
        rB2 = *(const float4*)(W + (size_t)(k0 + b_r2) * OUT_DIM + b_c4 * 4);
        rB3 = *(const float4*)(W + (size_t)(k0 + b_r3) * OUT_DIM + b_c4 * 4);
    };
    auto store_tiles = [&](int buf) {
        As[buf][(a_c0 * 4 + 0) * AS_LD + a_r0] = rA0.x;
        As[buf][(a_c0 * 4 + 1) * AS_LD + a_r0] = rA0.y;
        As[buf][(a_c0 * 4 + 2) * AS_LD + a_r0] = rA0.z;
        As[buf][(a_c0 * 4 + 3) * AS_LD + a_r0] = rA0.w;
        As[buf][(a_c0 * 4 + 0) * AS_LD + a_r1] = rA1.x;
        As[buf][(a_c0 * 4 + 1) * AS_LD + a_r1] = rA1.y;
        As[buf][(a_c0 * 4 + 2) * AS_LD + a_r1] = rA1.z;
        As[buf][(a_c0 * 4 + 3) * AS_LD + a_r1] = rA1.w;
        *(float4*)&Bs[buf][b_r0][b_c4 * 4] = rB0;
        *(float4*)&Bs[buf][b_r1][b_c4 * 4] = rB1;
        *(float4*)&Bs[buf][b_r2][b_c4 * 4] = rB2;
        *(float4*)&Bs[buf][b_r3][b_c4 * 4] = rB3;
    };

    float acc[4][4];
    #pragma unroll
    for (int i = 0; i < 4; i++)
        #pragma unroll
        for (int j = 0; j < 4; j++) acc[i][j] = 0.0f;

    load_tiles(0);
    store_tiles(0);
    __syncthreads();

    const int NT = IN_DIM / GM_BK;   // 8 k-tiles
    for (int t = 0; t < NT; t++) {
        int buf = t & 1;
        if (t + 1 < NT) load_tiles((t + 1) * GM_BK);

        #pragma unroll
        for (int k = 0; k < GM_BK; k++) {
            float4 av = *(const float4*)&As[buf][k * AS_LD + trow * 4];
            float4 bv = *(const float4*)&Bs[buf][k][tcol * 4];
            float aa[4] = {av.x, av.y, av.z, av.w};
            float bb[4] = {bv.x, bv.y, bv.z, bv.w};
            #pragma unroll
            for (int i = 0; i < 4; i++)
                #pragma unroll
                for (int j = 0; j < 4; j++)
                    acc[i][j] = fmaf(aa[i], bb[j], acc[i][j]);
        }
        if (t + 1 < NT) store_tiles(buf ^ 1);
        __syncthreads();
    }

    // ---- fused epilogue: store proj + compute s_i/s_j ----
    #pragma unroll
    for (int i = 0; i < 4; i++) {
        int row = block_row + trow * 4 + i;
        float4 vv = make_float4(acc[i][0], acc[i][1], acc[i][2], acc[i][3]);
        *(float4*)(g_proj + (size_t)row * OUT_DIM + tcol * 4) = vv;

        float q0 = acc[i][0] * a_s[tcol * 4 + 0] + acc[i][1] * a_s[tcol * 4 + 1]
                 + acc[i][2] * a_s[tcol * 4 + 2] + acc[i][3] * a_s[tcol * 4 + 3];
        float q1 = acc[i][0] * a_s[64 + tcol * 4 + 0] + acc[i][1] * a_s[64 + tcol * 4 + 1]
                 + acc[i][2] * a_s[64 + tcol * 4 + 2] + acc[i][3] * a_s[64 + tcol * 4 + 3];
        #pragma unroll
        for (int o = 8; o > 0; o >>= 1) {
            q0 += __shfl_down_sync(0xffffffffu, q0, o, 16);
            q1 += __shfl_down_sync(0xffffffffu, q1, o, 16);
        }
        if (tcol == 0) { g_si[row] = q0; g_sj[row] = q1; }
    }
}

// ---------------------------------------------------------------------------
// Kernel 2: per-row sparse softmax-attention — R3 version VERBATIM
// (measured 63.5 us; every attempted restructure regressed it).
// ---------------------------------------------------------------------------
#define CAP 1024

__device__ __forceinline__ float leaky(float x) {
    return x > 0.0f ? x : SLOPE * x;
}

__device__ __forceinline__ float block_reduce(float v, float* s8, bool do_max)
{
    int lane = threadIdx.x & 31;
    int warp = threadIdx.x >> 5;
    #pragma unroll
    for (int o = 16; o > 0; o >>= 1) {
        float t = __shfl_xor_sync(0xffffffffu, v, o);
        v = do_max ? fmaxf(v, t) : (v + t);
    }
    __syncthreads();
    if (lane == 0) s8[warp] = v;
    __syncthreads();
    if (threadIdx.x == 0) {
        float r = s8[0];
        #pragma unroll
        for (int w = 1; w < 8; w++)
            r = do_max ? fmaxf(r, s8[w]) : (r + s8[w]);
        s8[0] = r;
    }
    __syncthreads();
    return s8[0];
}

__global__ __launch_bounds__(256) void attn_kernel(
    const unsigned* __restrict__ adj, float* __restrict__ out)
{
    __shared__ int   s_idx[CAP];
    __shared__ float s_w[CAP];
    __shared__ float s_acc[4][OUT_DIM];
    __shared__ float s_red[8];
    __shared__ int   s_wsum[8];
    __shared__ int   s_woff[8];
    __shared__ int   s_cnt;

    const int row = blockIdx.x;
    const int tid = threadIdx.x;
    const int lane = tid & 31;
    const int warp = tid >> 5;

    const unsigned* arow = adj + (size_t)row * N_NODES;   // 8192 words = 32 KB
    const uint4* arow4 = (const uint4*)arow;

    // ---- pass 1: count edges per thread (8 uint4 = 32 elements each) ----
    int c = 0;
    #pragma unroll
    for (int it = 0; it < 8; it++) {
        uint4 v = arow4[tid + it * 256];
        c += (v.x != 0u) + (v.y != 0u) + (v.z != 0u) + (v.w != 0u);
    }

    // ---- block exclusive scan over per-thread counts ----
    int inc = c;
    #pragma unroll
    for (int o = 1; o < 32; o <<= 1) {
        int t = __shfl_up_sync(0xffffffffu, inc, o);
        if (lane >= o) inc += t;
    }
    if (lane == 31) s_wsum[warp] = inc;
    __syncthreads();
    if (tid == 0) {
        int s = 0;
        #pragma unroll
        for (int w = 0; w < 8; w++) { s_woff[w] = s; s += s_wsum[w]; }
        s_cnt = s;
    }
    __syncthreads();
    int off = s_woff[warp] + inc - c;   // exclusive prefix for this thread
    const int cnt = s_cnt;

    // ---- pass 2: ordered write of neighbor indices (row now in L1/L2) ----
    if (cnt <= CAP) {
        #pragma unroll
        for (int it = 0; it < 8; it++) {
            int i4 = tid + it * 256;
            uint4 v = arow4[i4];
            int base = i4 * 4;
            if (v.x) s_idx[off++] = base + 0;
            if (v.y) s_idx[off++] = base + 1;
            if (v.z) s_idx[off++] = base + 2;
            if (v.w) s_idx[off++] = base + 3;
        }
    }
    __syncthreads();

    const float si_r = g_si[row];
    const int   g    = tid >> 6;      // group 0..3
    const int   d    = tid & 63;      // output dim

    if (cnt == 0) {
        // softmax over all-NEG_BIG row is uniform: out = mean(proj)
        float acc = 0.0f;
        for (int j = g; j < N_NODES; j += 4)
            acc += g_proj[(size_t)j * OUT_DIM + d];
        s_acc[g][d] = acc;
        __syncthreads();
        if (g == 0) {
            float tot = s_acc[0][d] + s_acc[1][d] + s_acc[2][d] + s_acc[3][d];
            out[(size_t)row * OUT_DIM + d] = tot * (1.0f / (float)N_NODES);
        }
        return;
    }

    if (cnt <= CAP) {
        // ---- fast path: list-based softmax ----
        float lm = -INFINITY;
        for (int k = tid; k < cnt; k += 256) {
            float e = leaky(si_r + g_sj[s_idx[k]]);
            s_w[k] = e;
            lm = fmaxf(lm, e);
        }
        float m = block_reduce(lm, s_red, true);

        float ls = 0.0f;
        for (int k = tid; k < cnt; k += 256) {
            float w = __expf(s_w[k] - m);
            s_w[k] = w;
            ls += w;
        }
        float denom = block_reduce(ls, s_red, false);

        float acc = 0.0f;
        #pragma unroll 4
        for (int k = g; k < cnt; k += 4)
            acc += s_w[k] * g_proj[(size_t)s_idx[k] * OUT_DIM + d];
        s_acc[g][d] = acc;
        __syncthreads();
        if (g == 0) {
            float tot = s_acc[0][d] + s_acc[1][d] + s_acc[2][d] + s_acc[3][d];
            out[(size_t)row * OUT_DIM + d] = tot / denom;
        }
        return;
    }

    // ---- overflow fallback (cnt > CAP, not expected at p=0.01) ----
    float lm = -INFINITY;
    for (int j = tid; j < N_NODES; j += 256)
        if (arow[j]) lm = fmaxf(lm, leaky(si_r + g_sj[j]));
    float m = block_reduce(lm, s_red, true);

    float ls = 0.0f;
    for (int j = tid; j < N_NODES; j += 256)
        if (arow[j]) ls += __expf(leaky(si_r + g_sj[j]) - m);
    float denom = block_reduce(ls, s_red, false);

    float acc = 0.0f;
    for (int j = g; j < N_NODES; j += 4)
        if (arow[j]) {
            float w = __expf(leaky(si_r + g_sj[j]) - m);
            acc += w * g_proj[(size_t)j * OUT_DIM + d];
        }
    s_acc[g][d] = acc;
    __syncthreads();
    if (g == 0) {
        float tot = s_acc[0][d] + s_acc[1][d] + s_acc[2][d] + s_acc[3][d];
        out[(size_t)row * OUT_DIM + d] = tot / denom;
    }
}

// ---------------------------------------------------------------------------
// Launch
// ---------------------------------------------------------------------------
extern "C" void kernel_launch(void* const* d_in, const int* in_sizes, int n_in,
                              void* d_out, int out_size)
{
    const float*    X   = (const float*)d_in[0];
    const unsigned* adj = (const unsigned*)d_in[1];   // bool widened to 32-bit
    const float*    W   = (const float*)d_in[2];
    const float*    a   = (const float*)d_in[3];
    float*          out = (float*)d_out;

    gemm_proj_kernel<<<N_NODES / GM_BM, 128>>>(X, W, a);
    attn_kernel<<<N_NODES, 256>>>(adj, out);
}

// round 9
// speedup vs baseline: 1.8660x; 1.0904x over previous
#include <cuda_runtime.h>
#include <cstdint>

// Problem constants (fixed by setup_inputs)
#define N_NODES 8192
#define IN_DIM  256
#define OUT_DIM 64
#define SLOPE   0.2f

// Scratch (allocation-free rule: __device__ globals)
__device__ float g_proj[N_NODES * OUT_DIM];   // 2 MB
__device__ float g_si[N_NODES];
__device__ float g_sj[N_NODES];

// ---------------------------------------------------------------------------
// Kernel 1: proj = X[8192,256] @ W[256,64] + fused s_i/s_j epilogue.
// (R8 version verbatim — measured ~10.8 us, frozen.)
// ---------------------------------------------------------------------------
#define GM_BM 32
#define GM_BK 32
#define AS_LD 36   // 32 + 4 pad

__global__ __launch_bounds__(128) void gemm_proj_kernel(
    const float* __restrict__ X, const float* __restrict__ W,
    const float* __restrict__ a)
{
    __shared__ float As[2][GM_BK * AS_LD];   // [k][m], padded
    __shared__ float Bs[2][GM_BK][OUT_DIM];  // [k][n]
    __shared__ float a_s[2 * OUT_DIM];

    const int tid = threadIdx.x;
    const int block_row = blockIdx.x * GM_BM;
    const int trow = tid >> 4;   // 0..7
    const int tcol = tid & 15;   // 0..15

    a_s[tid] = a[tid];

    const int a_r0 = tid >> 3;
    const int a_c0 = tid & 7;
    const int a_r1 = (tid + 128) >> 3;
    const int b_c4 = tid & 15;
    const int b_r0 = tid >> 4;
    const int b_r1 = (tid + 128) >> 4;
    const int b_r2 = (tid + 256) >> 4;
    const int b_r3 = (tid + 384) >> 4;

    float4 rA0, rA1, rB0, rB1, rB2, rB3;

    auto load_tiles = [&](int k0) {
        rA0 = *(const float4*)(X + (size_t)(block_row + a_r0) * IN_DIM + k0 + a_c0 * 4);
        rA1 = *(const float4*)(X + (size_t)(block_row + a_r1) * IN_DIM + k0 + a_c0 * 4);
        rB0 = *(const float4*)(W + (size_t)(k0 + b_r0) * OUT_DIM + b_c4 * 4);
        rB1 = *(const float4*)(W + (size_t)(k0 + b_r1) * OUT_DIM + b_c4 * 4);
        rB2 = *(const float4*)(W + (size_t)(k0 + b_r2) * OUT_DIM + b_c4 * 4);
        rB3 = *(const float4*)(W + (size_t)(k0 + b_r3) * OUT_DIM + b_c4 * 4);
    };
    auto store_tiles = [&](int buf) {
        As[buf][(a_c0 * 4 + 0) * AS_LD + a_r0] = rA0.x;
        As[buf][(a_c0 * 4 + 1) * AS_LD + a_r0] = rA0.y;
        As[buf][(a_c0 * 4 + 2) * AS_LD + a_r0] = rA0.z;
        As[buf][(a_c0 * 4 + 3) * AS_LD + a_r0] = rA0.w;
        As[buf][(a_c0 * 4 + 0) * AS_LD + a_r1] = rA1.x;
        As[buf][(a_c0 * 4 + 1) * AS_LD + a_r1] = rA1.y;
        As[buf][(a_c0 * 4 + 2) * AS_LD + a_r1] = rA1.z;
        As[buf][(a_c0 * 4 + 3) * AS_LD + a_r1] = rA1.w;
        *(float4*)&Bs[buf][b_r0][b_c4 * 4] = rB0;
        *(float4*)&Bs[buf][b_r1][b_c4 * 4] = rB1;
        *(float4*)&Bs[buf][b_r2][b_c4 * 4] = rB2;
        *(float4*)&Bs[buf][b_r3][b_c4 * 4] = rB3;
    };

    float acc[4][4];
    #pragma unroll
    for (int i = 0; i < 4; i++)
        #pragma unroll
        for (int j = 0; j < 4; j++) acc[i][j] = 0.0f;

    load_tiles(0);
    store_tiles(0);
    __syncthreads();

    const int NT = IN_DIM / GM_BK;
    for (int t = 0; t < NT; t++) {
        int buf = t & 1;
        if (t + 1 < NT) load_tiles((t + 1) * GM_BK);

        #pragma unroll
        for (int k = 0; k < GM_BK; k++) {
            float4 av = *(const float4*)&As[buf][k * AS_LD + trow * 4];
            float4 bv = *(const float4*)&Bs[buf][k][tcol * 4];
            float aa[4] = {av.x, av.y, av.z, av.w};
            float bb[4] = {bv.x, bv.y, bv.z, bv.w};
            #pragma unroll
            for (int i = 0; i < 4; i++)
                #pragma unroll
                for (int j = 0; j < 4; j++)
                    acc[i][j] = fmaf(aa[i], bb[j], acc[i][j]);
        }
        if (t + 1 < NT) store_tiles(buf ^ 1);
        __syncthreads();
    }

    #pragma unroll
    for (int i = 0; i < 4; i++) {
        int row = block_row + trow * 4 + i;
        float4 vv = make_float4(acc[i][0], acc[i][1], acc[i][2], acc[i][3]);
        *(float4*)(g_proj + (size_t)row * OUT_DIM + tcol * 4) = vv;

        float q0 = acc[i][0] * a_s[tcol * 4 + 0] + acc[i][1] * a_s[tcol * 4 + 1]
                 + acc[i][2] * a_s[tcol * 4 + 2] + acc[i][3] * a_s[tcol * 4 + 3];
        float q1 = acc[i][0] * a_s[64 + tcol * 4 + 0] + acc[i][1] * a_s[64 + tcol * 4 + 1]
                 + acc[i][2] * a_s[64 + tcol * 4 + 2] + acc[i][3] * a_s[64 + tcol * 4 + 3];
        #pragma unroll
        for (int o = 8; o > 0; o >>= 1) {
            q0 += __shfl_down_sync(0xffffffffu, q0, o, 16);
            q1 += __shfl_down_sync(0xffffffffu, q1, o, 16);
        }
        if (tcol == 0) { g_si[row] = q0; g_sj[row] = q1; }
    }
}

// ---------------------------------------------------------------------------
// Kernel 2: per-row sparse softmax-attention.
// R3 structure, but SINGLE-PASS scan: each thread packs its 32 words'
// nonzero flags into one register bitmask; the compaction walks set bits
// (expected 0.32/thread) instead of re-reading 32 KB from L1 and running
// 32 predicated branches. Bit order == old visit order -> identical output.
// ---------------------------------------------------------------------------
#define CAP 1024

__device__ __forceinline__ float leaky(float x) {
    return x > 0.0f ? x : SLOPE * x;
}

__device__ __forceinline__ float block_reduce(float v, float* s8, bool do_max)
{
    int lane = threadIdx.x & 31;
    int warp = threadIdx.x >> 5;
    #pragma unroll
    for (int o = 16; o > 0; o >>= 1) {
        float t = __shfl_xor_sync(0xffffffffu, v, o);
        v = do_max ? fmaxf(v, t) : (v + t);
    }
    __syncthreads();
    if (lane == 0) s8[warp] = v;
    __syncthreads();
    if (threadIdx.x == 0) {
        float r = s8[0];
        #pragma unroll
        for (int w = 1; w < 8; w++)
            r = do_max ? fmaxf(r, s8[w]) : (r + s8[w]);
        s8[0] = r;
    }
    __syncthreads();
    return s8[0];
}

__global__ __launch_bounds__(256) void attn_kernel(
    const unsigned* __restrict__ adj, float* __restrict__ out)
{
    __shared__ int   s_idx[CAP];
    __shared__ float s_w[CAP];
    __shared__ float s_acc[4][OUT_DIM];
    __shared__ float s_red[8];
    __shared__ int   s_wsum[8];
    __shared__ int   s_woff[8];
    __shared__ int   s_cnt;

    const int row = blockIdx.x;
    const int tid = threadIdx.x;
    const int lane = tid & 31;
    const int warp = tid >> 5;

    const unsigned* arow = adj + (size_t)row * N_NODES;   // 8192 words = 32 KB
    const uint4* arow4 = (const uint4*)arow;

    // ---- single pass: stream 8 uint4 / thread, pack nonzero flags ----
    unsigned mask = 0;
    #pragma unroll
    for (int it = 0; it < 8; it++) {
        uint4 v = arow4[tid + it * 256];
        unsigned b = (v.x != 0u ? 1u : 0u)
                   | (v.y != 0u ? 2u : 0u)
                   | (v.z != 0u ? 4u : 0u)
                   | (v.w != 0u ? 8u : 0u);
        mask |= b << (it * 4);
    }
    const int c = __popc(mask);

    // ---- block exclusive scan over per-thread counts ----
    int inc = c;
    #pragma unroll
    for (int o = 1; o < 32; o <<= 1) {
        int t = __shfl_up_sync(0xffffffffu, inc, o);
        if (lane >= o) inc += t;
    }
    if (lane == 31) s_wsum[warp] = inc;
    __syncthreads();
    if (tid == 0) {
        int s = 0;
        #pragma unroll
        for (int w = 0; w < 8; w++) { s_woff[w] = s; s += s_wsum[w]; }
        s_cnt = s;
    }
    __syncthreads();
    int off = s_woff[warp] + inc - c;   // exclusive prefix for this thread
    const int cnt = s_cnt;

    // ---- compaction from the bitmask (no adjacency re-read) ----
    if (cnt <= CAP) {
        unsigned m = mask;
        while (m) {
            int p = __ffs(m) - 1;          // ascending: same order as before
            m &= m - 1;
            // bit p covers word 4*(tid + (p>>2)*256) + (p&3)
            s_idx[off++] = 4 * tid + (p >> 2) * 1024 + (p & 3);
        }
    }
    __syncthreads();

    const float si_r = g_si[row];
    const int   g    = tid >> 6;      // group 0..3
    const int   d    = tid & 63;      // output dim

    if (cnt == 0) {
        // softmax over all-NEG_BIG row is uniform: out = mean(proj)
        float acc = 0.0f;
        for (int j = g; j < N_NODES; j += 4)
            acc += g_proj[(size_t)j * OUT_DIM + d];
        s_acc[g][d] = acc;
        __syncthreads();
        if (g == 0) {
            float tot = s_acc[0][d] + s_acc[1][d] + s_acc[2][d] + s_acc[3][d];
            out[(size_t)row * OUT_DIM + d] = tot * (1.0f / (float)N_NODES);
        }
        return;
    }

    if (cnt <= CAP) {
        // ---- fast path: list-based softmax ----
        float lm = -INFINITY;
        for (int k = tid; k < cnt; k += 256) {
            float e = leaky(si_r + g_sj[s_idx[k]]);
            s_w[k] = e;
            lm = fmaxf(lm, e);
        }
        float m = block_reduce(lm, s_red, true);

        float ls = 0.0f;
        for (int k = tid; k < cnt; k += 256) {
            float w = __expf(s_w[k] - m);
            s_w[k] = w;
            ls += w;
        }
        float denom = block_reduce(ls, s_red, false);

        float acc = 0.0f;
        #pragma unroll 4
        for (int k = g; k < cnt; k += 4)
            acc += s_w[k] * g_proj[(size_t)s_idx[k] * OUT_DIM + d];
        s_acc[g][d] = acc;
        __syncthreads();
        if (g == 0) {
            float tot = s_acc[0][d] + s_acc[1][d] + s_acc[2][d] + s_acc[3][d];
            out[(size_t)row * OUT_DIM + d] = tot / denom;
        }
        return;
    }

    // ---- overflow fallback (cnt > CAP, not expected at p=0.01) ----
    float lm = -INFINITY;
    for (int j = tid; j < N_NODES; j += 256)
        if (arow[j]) lm = fmaxf(lm, leaky(si_r + g_sj[j]));
    float m = block_reduce(lm, s_red, true);

    float ls = 0.0f;
    for (int j = tid; j < N_NODES; j += 256)
        if (arow[j]) ls += __expf(leaky(si_r + g_sj[j]) - m);
    float denom = block_reduce(ls, s_red, false);

    float acc = 0.0f;
    for (int j = g; j < N_NODES; j += 4)
        if (arow[j]) {
            float w = __expf(leaky(si_r + g_sj[j]) - m);
            acc += w * g_proj[(size_t)j * OUT_DIM + d];
        }
    s_acc[g][d] = acc;
    __syncthreads();
    if (g == 0) {
        float tot = s_acc[0][d] + s_acc[1][d] + s_acc[2][d] + s_acc[3][d];
        out[(size_t)row * OUT_DIM + d] = tot / denom;
    }
}

// ---------------------------------------------------------------------------
// Launch
// ---------------------------------------------------------------------------
extern "C" void kernel_launch(void* const* d_in, const int* in_sizes, int n_in,
                              void* d_out, int out_size)
{
    const float*    X   = (const float*)d_in[0];
    const unsigned* adj = (const unsigned*)d_in[1];   // bool widened to 32-bit
    const float*    W   = (const float*)d_in[2];
    const float*    a   = (const float*)d_in[3];
    float*          out = (float*)d_out;

    gemm_proj_kernel<<<N_NODES / GM_BM, 128>>>(X, W, a);
    attn_kernel<<<N_NODES, 256>>>(adj, out);
}